// round 15
// baseline (speedup 1.0000x reference)
#include <cuda_runtime.h>
#include <cuda_fp16.h>

#define NN 200000
#define NE 3200000
#define F  30
#define FS 32          // padded feature stride
#define PAD 64         // padded CSR slots per node (max deg ~36 for Poisson(16))
#define NBLK1 592      // agg1 persistent grid (~4 blocks/SM)
#define NBLK2 1184     // agg2 persistent grid (8 blocks/SM)

// ---- scratch (device globals; no allocation allowed) ----
__device__ int    g_is64;
__device__ int    g_deg[NN];
__device__ int    g_cursor[NN];
__device__ float  g_dinv[NN];
__device__ float  g_xs[NN * 2];      // x * dinv (layer-1 aggregation operand)
__device__ int    g_csr[NN * PAD];   // padded CSR: node d owns [d*PAD, d*PAD+deg)
__device__ __half g_feat[NN * FS];   // layer-2 pre-scaled features (fp16, 64B rows)
__device__ float  g_scal[NN];        // layer-3 scalar features

// ---------------- init: cursor bases + dtype detect ----------------

__global__ void k_init(const void* __restrict__ ei, int E) {
    int i = blockIdx.x * blockDim.x + threadIdx.x;
    if (i < NN) g_cursor[i] = i * PAD;
    if (i == 0) {
        const long long* p = (const long long*)ei;
        int ok64 = 1;
        int n = (E < 64) ? E : 64;
        for (int k = 0; k < n; k++) {
            long long v = p[k];
            if (v < 0 || v >= NN) { ok64 = 0; break; }
        }
        g_is64 = ok64;
    }
}

// ---------------- scatter into padded CSR (converts inline) ----------------

__global__ void k_scatter(const void* __restrict__ ei, int E) {
    int is64 = g_is64;
    const long long* p64 = (const long long*)ei;
    const int*       p32 = (const int*)ei;
    for (int e = blockIdx.x * blockDim.x + threadIdx.x; e < E;
         e += gridDim.x * blockDim.x) {
        int s, d;
        if (is64) { s = (int)p64[e]; d = (int)p64[E + e]; }
        else      { s = p32[e];      d = p32[E + e]; }
        if ((unsigned)s >= NN) s = 0;
        if ((unsigned)d >= NN) d = 0;
        int pos = atomicAdd(&g_cursor[d], 1);
        if (pos < (d + 1) * PAD) g_csr[pos] = s;   // overflow guard (p ~ 0)
    }
}

// ---------------- finalize: deg, dinv, xs ----------------

__global__ void k_fin(const float* __restrict__ x) {
    int i = blockIdx.x * blockDim.x + threadIdx.x;
    if (i >= NN) return;
    int dg = g_cursor[i] - i * PAD;
    if (dg > PAD) dg = PAD;
    g_deg[i] = dg;
    float di = rsqrtf((float)(dg + 1));   // +1 self-loop
    g_dinv[i] = di;
    g_xs[2 * i]     = x[2 * i]     * di;
    g_xs[2 * i + 1] = x[2 * i + 1] * di;
}

// ---------------- layer 1 agg + fused layer-2 transform --------------------
// Persistent, dual-node pipelined. W2 column in registers (32/lane);
// cat delivered via LDS.128 broadcasts (16 wf per node-pair).

__global__ void __launch_bounds__(256)
k_agg1(const float* __restrict__ x, const float* __restrict__ W1,
       const float* __restrict__ b1, const float* __restrict__ W2) {
    __shared__ __align__(16) float scat[8][64];   // [warp][node0:0-31, node1:32-63]

    int w = threadIdx.x >> 5;
    int lane = threadIdx.x & 31;
    int f = (lane < F) ? lane : 0;

    // per-lane weights/bias in registers (loop-invariant)
    float w1a = W1[f], w1b = W1[30 + f];
    float bbr = (lane < F) ? b1[lane] : 0.f;
    float wreg[32];
#pragma unroll
    for (int k = 0; k < 32; k++) wreg[k] = W2[k * 30 + f];

    const int STRIDE = gridDim.x << 3;

    for (int d0 = (blockIdx.x << 3) + w; d0 < NN; d0 += 2 * STRIDE) {
        int d1 = d0 + STRIDE;
        bool v1 = (d1 < NN);

        int cnt0 = g_deg[d0];
        int cnt1 = v1 ? g_deg[d1] : 0;
        int base0 = d0 * PAD, base1 = d1 * PAD;
        int mx = max(cnt0, cnt1);

        float a00 = 0.f, a01 = 0.f, a10 = 0.f, a11 = 0.f;
        for (int i = lane; i < mx; i += 32) {
            if (i < cnt0) {
                float2 v = ((const float2*)g_xs)[g_csr[base0 + i]];
                a00 += v.x; a01 += v.y;
            }
            if (i < cnt1) {
                float2 v = ((const float2*)g_xs)[g_csr[base1 + i]];
                a10 += v.x; a11 += v.y;
            }
        }
#pragma unroll
        for (int st = 16; st > 0; st >>= 1) {
            a00 += __shfl_xor_sync(0xffffffffu, a00, st);
            a01 += __shfl_xor_sync(0xffffffffu, a01, st);
            a10 += __shfl_xor_sync(0xffffffffu, a10, st);
            a11 += __shfl_xor_sync(0xffffffffu, a11, st);
        }

        float2 self0 = ((const float2*)g_xs)[d0];
        float  di0   = g_dinv[d0];
        float s00 = (a00 + self0.x) * di0;
        float s01 = (a01 + self0.y) * di0;

        float2 self1 = v1 ? ((const float2*)g_xs)[d1] : make_float2(0.f, 0.f);
        float  di1   = v1 ? g_dinv[d1] : 0.f;
        float s10 = (a10 + self1.x) * di1;
        float s11 = (a11 + self1.y) * di1;

        float cat0, cat1;
        if (lane < F) {
            cat0 = fmaxf(fmaf(s00, w1a, fmaf(s01, w1b, bbr)), 0.f);
            cat1 = fmaxf(fmaf(s10, w1a, fmaf(s11, w1b, bbr)), 0.f);
        } else {
            cat0 = x[2 * d0 + (lane - 30)];
            cat1 = v1 ? x[2 * d1 + (lane - 30)] : 0.f;
        }
        scat[w][lane]      = cat0;
        scat[w][32 + lane] = cat1;
        __syncwarp();

        // transform: 16 LDS.128 broadcasts + 64 FMA (register weights)
        const float4* sc4 = (const float4*)scat[w];
        float acc0 = 0.f, acc1 = 0.f;
#pragma unroll
        for (int k4 = 0; k4 < 8; k4++) {
            float4 c0 = sc4[k4];
            float4 c1 = sc4[8 + k4];
            acc0 = fmaf(c0.x, wreg[4 * k4],     acc0);
            acc0 = fmaf(c0.y, wreg[4 * k4 + 1], acc0);
            acc0 = fmaf(c0.z, wreg[4 * k4 + 2], acc0);
            acc0 = fmaf(c0.w, wreg[4 * k4 + 3], acc0);
            acc1 = fmaf(c1.x, wreg[4 * k4],     acc1);
            acc1 = fmaf(c1.y, wreg[4 * k4 + 1], acc1);
            acc1 = fmaf(c1.z, wreg[4 * k4 + 2], acc1);
            acc1 = fmaf(c1.w, wreg[4 * k4 + 3], acc1);
        }
        g_feat[d0 * FS + lane] = __float2half((lane < F) ? acc0 * di0 : 0.f);
        if (v1)
            g_feat[d1 * FS + lane] = __float2half((lane < F) ? acc1 * di1 : 0.f);
        __syncwarp();   // protect scat before next overwrite
    }
}

// ---------------- layer 2 agg (dual-node) + fused layer-3 transform --------

__global__ void __launch_bounds__(256)
k_agg2(const float* __restrict__ x, const float* __restrict__ b2,
       const float* __restrict__ W3) {
    __shared__ int sidx[8][2 * PAD];   // [warp][node0:0-63, node1:64-127]

    int w = threadIdx.x >> 5;
    int lane = threadIdx.x & 31;
    float bbr = (lane < F) ? b2[lane] : 0.f;
    float w3r = W3[lane];

    const int STRIDE = gridDim.x << 3;

    for (int d0 = (blockIdx.x << 3) + w; d0 < NN; d0 += 2 * STRIDE) {
        int d1 = d0 + STRIDE;
        bool v1 = (d1 < NN);

        int cnt0 = g_deg[d0];
        int cnt1 = v1 ? g_deg[d1] : 0;
        int base0 = d0 * PAD, base1 = d1 * PAD;

        if (lane < cnt0)      sidx[w][lane]          = g_csr[base0 + lane];
        if (lane + 32 < cnt0) sidx[w][lane + 32]     = g_csr[base0 + lane + 32];
        if (lane < cnt1)      sidx[w][64 + lane]     = g_csr[base1 + lane];
        if (lane + 32 < cnt1) sidx[w][96 + lane]     = g_csr[base1 + lane + 32];
        __syncwarp();

        float acc0 = __half2float(g_feat[d0 * FS + lane]);          // self-loop
        float acc1 = v1 ? __half2float(g_feat[d1 * FS + lane]) : 0.f;
        int mx = max(cnt0, cnt1);
        for (int j = 0; j < mx; j++) {
            if (j < cnt0) acc0 += __half2float(g_feat[sidx[w][j] * FS + lane]);
            if (j < cnt1) acc1 += __half2float(g_feat[sidx[w][64 + j] * FS + lane]);
        }

        float di0 = g_dinv[d0];
        float di1 = v1 ? g_dinv[d1] : 0.f;
        float cat0, cat1;
        if (lane < F) {
            cat0 = fmaxf(fmaf(acc0, di0, bbr), 0.f);
            cat1 = fmaxf(fmaf(acc1, di1, bbr), 0.f);
        } else {
            cat0 = x[2 * d0 + (lane - 30)];
            cat1 = v1 ? x[2 * d1 + (lane - 30)] : 0.f;
        }

        float p0 = cat0 * w3r;
        float p1 = cat1 * w3r;
#pragma unroll
        for (int st = 16; st > 0; st >>= 1) {
            p0 += __shfl_xor_sync(0xffffffffu, p0, st);
            p1 += __shfl_xor_sync(0xffffffffu, p1, st);
        }
        if (lane == 0) {
            g_scal[d0] = p0 * di0;
            if (v1) g_scal[d1] = p1 * di1;
        }
        __syncwarp();
    }
}

// ---------------- layer 3 aggregation (16-lane group per node) -------------

__global__ void k_agg3(const float* __restrict__ b3, float* __restrict__ out) {
    int d = (blockIdx.x * blockDim.x + threadIdx.x) >> 4;
    int lane = threadIdx.x & 15;
    int gb = threadIdx.x & 16;
    unsigned gmask = 0xffffu << gb;
    if (d >= NN) return;
    int start = d * PAD, cnt = g_deg[d];
    float acc = 0.f;
    for (int idx = lane; idx < cnt; idx += 16)
        acc += g_scal[g_csr[start + idx]];
#pragma unroll
    for (int st = 8; st > 0; st >>= 1)
        acc += __shfl_xor_sync(gmask, acc, st);
    if (lane == 0) out[d] = g_dinv[d] * (acc + g_scal[d]) + b3[0];
}

// ---------------- launch ----------------

extern "C" void kernel_launch(void* const* d_in, const int* in_sizes, int n_in,
                              void* d_out, int out_size) {
    const float* x  = (const float*)d_in[0];
    const void*  ei = d_in[1];
    const float* W1 = (const float*)d_in[2];
    const float* b1 = (const float*)d_in[3];
    const float* W2 = (const float*)d_in[4];
    const float* b2 = (const float*)d_in[5];
    const float* W3 = (const float*)d_in[6];
    const float* b3 = (const float*)d_in[7];
    float* out = (float*)d_out;

    int E = in_sizes[1] / 2;
    if (E > NE) E = NE;

    k_init<<<(NN + 255) / 256, 256>>>(ei, E);
    k_scatter<<<2048, 256>>>(ei, E);
    k_fin<<<(NN + 255) / 256, 256>>>(x);

    int a3N = (NN * 16 + 255) / 256;      // 16-lane-group grid

    k_agg1<<<NBLK1, 256>>>(x, W1, b1, W2); // layer 1 agg + layer 2 transform
    k_agg2<<<NBLK2, 256>>>(x, b2, W3);     // layer 2 agg + layer 3 transform
    k_agg3<<<a3N, 256>>>(b3, out);         // layer 3 agg -> output
}

// round 16
// speedup vs baseline: 1.6357x; 1.6357x over previous
#include <cuda_runtime.h>
#include <cuda_fp16.h>

#define NN 200000
#define NE 3200000
#define F  30
#define FS 32          // padded feature stride
#define PAD 64         // padded CSR slots per node (max deg ~36 for Poisson(16))
#define NBLK 1184      // persistent grid (8 blocks/SM x 148 SMs)

// ---- scratch (device globals; no allocation allowed) ----
__device__ int    g_is64;
__device__ int    g_deg[NN];
__device__ int    g_cursor[NN];
__device__ float  g_dinv[NN];
__device__ float  g_xs[NN * 2];      // x * dinv (layer-1 aggregation operand)
__device__ int    g_csr[NN * PAD];   // padded CSR: node d owns [d*PAD, d*PAD+deg)
__device__ __half g_feat[NN * FS];   // layer-2 pre-scaled features (fp16, 64B rows)
__device__ float  g_scal[NN];        // layer-3 scalar features

// ---------------- init: cursor bases + dtype detect ----------------

__global__ void k_init(const void* __restrict__ ei, int E) {
    int i = blockIdx.x * blockDim.x + threadIdx.x;
    if (i < NN) g_cursor[i] = i * PAD;
    if (i == 0) {
        const long long* p = (const long long*)ei;
        int ok64 = 1;
        int n = (E < 64) ? E : 64;
        for (int k = 0; k < n; k++) {
            long long v = p[k];
            if (v < 0 || v >= NN) { ok64 = 0; break; }
        }
        g_is64 = ok64;
    }
}

// ---------------- scatter into padded CSR (converts inline) ----------------

__global__ void k_scatter(const void* __restrict__ ei, int E) {
    int is64 = g_is64;
    const long long* p64 = (const long long*)ei;
    const int*       p32 = (const int*)ei;
    for (int e = blockIdx.x * blockDim.x + threadIdx.x; e < E;
         e += gridDim.x * blockDim.x) {
        int s, d;
        if (is64) { s = (int)p64[e]; d = (int)p64[E + e]; }
        else      { s = p32[e];      d = p32[E + e]; }
        if ((unsigned)s >= NN) s = 0;
        if ((unsigned)d >= NN) d = 0;
        int pos = atomicAdd(&g_cursor[d], 1);
        if (pos < (d + 1) * PAD) g_csr[pos] = s;   // overflow guard (p ~ 0)
    }
}

// ---------------- finalize: deg, dinv, xs ----------------

__global__ void k_fin(const float* __restrict__ x) {
    int i = blockIdx.x * blockDim.x + threadIdx.x;
    if (i >= NN) return;
    int dg = g_cursor[i] - i * PAD;
    if (dg > PAD) dg = PAD;
    g_deg[i] = dg;
    float di = rsqrtf((float)(dg + 1));   // +1 self-loop
    g_dinv[i] = di;
    g_xs[2 * i]     = x[2 * i]     * di;
    g_xs[2 * i + 1] = x[2 * i + 1] * di;
}

// ---------------- layer 1 agg (input space) + fused layer-2 transform ------
// Persistent; FOUR nodes per warp-iteration, interleaved register streams.

__global__ void __launch_bounds__(256)
k_agg1(const float* __restrict__ x, const float* __restrict__ W1,
       const float* __restrict__ b1, const float* __restrict__ W2) {
    __shared__ float w1[64];
    __shared__ float bb[32];
    __shared__ float w2[32 * 30];
    if (threadIdx.x < 60) w1[threadIdx.x] = W1[threadIdx.x];
    if (threadIdx.x < 30) bb[threadIdx.x] = b1[threadIdx.x];
    for (int j = threadIdx.x; j < 960; j += blockDim.x) w2[j] = W2[j];
    __syncthreads();

    int w = threadIdx.x >> 5;
    int lane = threadIdx.x & 31;
    int f = (lane < F) ? lane : 0;
    const int S = NBLK << 3;

    for (int d0 = (blockIdx.x << 3) + w; d0 < NN; d0 += 4 * S) {
        int  dd[4];
        bool vv[4];
        int  cnt[4], base[4];
        float ax[4], ay[4];
#pragma unroll
        for (int u = 0; u < 4; u++) {
            dd[u] = d0 + u * S;
            vv[u] = (dd[u] < NN);
            cnt[u] = vv[u] ? g_deg[dd[u]] : 0;
            base[u] = dd[u] * PAD;
            ax[u] = 0.f; ay[u] = 0.f;
        }
        int mx = max(max(cnt[0], cnt[1]), max(cnt[2], cnt[3]));

        for (int i = lane; i < mx; i += 32) {
#pragma unroll
            for (int u = 0; u < 4; u++) {
                if (i < cnt[u]) {
                    float2 v = ((const float2*)g_xs)[g_csr[base[u] + i]];
                    ax[u] += v.x; ay[u] += v.y;
                }
            }
        }
#pragma unroll
        for (int st = 16; st > 0; st >>= 1) {
#pragma unroll
            for (int u = 0; u < 4; u++) {
                ax[u] += __shfl_xor_sync(0xffffffffu, ax[u], st);
                ay[u] += __shfl_xor_sync(0xffffffffu, ay[u], st);
            }
        }

        float cat[4], di[4];
#pragma unroll
        for (int u = 0; u < 4; u++) {
            float2 self = vv[u] ? ((const float2*)g_xs)[dd[u]] : make_float2(0.f, 0.f);
            di[u] = vv[u] ? g_dinv[dd[u]] : 0.f;
            float s0 = (ax[u] + self.x) * di[u];
            float s1 = (ay[u] + self.y) * di[u];
            if (lane < F)
                cat[u] = fmaxf(fmaf(s0, w1[lane], fmaf(s1, w1[30 + lane], bb[lane])), 0.f);
            else
                cat[u] = vv[u] ? x[2 * dd[u] + (lane - 30)] : 0.f;
        }

        float acc[4] = {0.f, 0.f, 0.f, 0.f};
#pragma unroll
        for (int k = 0; k < 32; k++) {
            float wk = w2[k * 30 + f];
#pragma unroll
            for (int u = 0; u < 4; u++) {
                float c = __shfl_sync(0xffffffffu, cat[u], k);
                acc[u] = fmaf(c, wk, acc[u]);
            }
        }
#pragma unroll
        for (int u = 0; u < 4; u++) {
            if (vv[u])
                g_feat[dd[u] * FS + lane] =
                    __float2half((lane < F) ? acc[u] * di[u] : 0.f);
        }
    }
}

// ---------------- layer 2 agg (persistent, smem idx) + layer-3 transform ---

__global__ void __launch_bounds__(256)
k_agg2(const float* __restrict__ x, const float* __restrict__ b2,
       const float* __restrict__ W3) {
    __shared__ float bb[32];
    __shared__ float w3[32];
    __shared__ int   sidx[8][PAD];
    if (threadIdx.x < 30) bb[threadIdx.x] = b2[threadIdx.x];
    if (threadIdx.x < 32) w3[threadIdx.x] = W3[threadIdx.x];
    __syncthreads();

    int w = threadIdx.x >> 5;
    int lane = threadIdx.x & 31;

    for (int d = (blockIdx.x << 3) + w; d < NN; d += (NBLK << 3)) {
        int start = d * PAD, cnt = g_deg[d];
        if (lane < cnt) sidx[w][lane] = g_csr[start + lane];
        if (lane + 32 < cnt) sidx[w][lane + 32] = g_csr[start + lane + 32];
        __syncwarp();

        float acc0 = __half2float(g_feat[d * FS + lane]);   // self-loop term
        float acc1 = 0.f;
        int j = 0;
        for (; j + 1 < cnt; j += 2) {
            int s0 = sidx[w][j];
            int s1 = sidx[w][j + 1];
            acc0 += __half2float(g_feat[s0 * FS + lane]);
            acc1 += __half2float(g_feat[s1 * FS + lane]);
        }
        if (j < cnt) acc0 += __half2float(g_feat[sidx[w][j] * FS + lane]);
        float acc = acc0 + acc1;

        float di = g_dinv[d];
        float cat;
        if (lane < F) cat = fmaxf(fmaf(acc, di, bb[lane]), 0.f);
        else          cat = x[2 * d + (lane - 30)];

        float p = cat * w3[lane];
#pragma unroll
        for (int st = 16; st > 0; st >>= 1)
            p += __shfl_xor_sync(0xffffffffu, p, st);
        if (lane == 0) g_scal[d] = p * di;
        __syncwarp();
    }
}

// ---------------- layer 3 aggregation (16-lane group per node) -------------

__global__ void k_agg3(const float* __restrict__ b3, float* __restrict__ out) {
    int d = (blockIdx.x * blockDim.x + threadIdx.x) >> 4;
    int lane = threadIdx.x & 15;
    int gb = threadIdx.x & 16;
    unsigned gmask = 0xffffu << gb;
    if (d >= NN) return;
    int start = d * PAD, cnt = g_deg[d];
    float acc = 0.f;
    for (int idx = lane; idx < cnt; idx += 16)
        acc += g_scal[g_csr[start + idx]];
#pragma unroll
    for (int st = 8; st > 0; st >>= 1)
        acc += __shfl_xor_sync(gmask, acc, st);
    if (lane == 0) out[d] = g_dinv[d] * (acc + g_scal[d]) + b3[0];
}

// ---------------- launch ----------------

extern "C" void kernel_launch(void* const* d_in, const int* in_sizes, int n_in,
                              void* d_out, int out_size) {
    const float* x  = (const float*)d_in[0];
    const void*  ei = d_in[1];
    const float* W1 = (const float*)d_in[2];
    const float* b1 = (const float*)d_in[3];
    const float* W2 = (const float*)d_in[4];
    const float* b2 = (const float*)d_in[5];
    const float* W3 = (const float*)d_in[6];
    const float* b3 = (const float*)d_in[7];
    float* out = (float*)d_out;

    int E = in_sizes[1] / 2;
    if (E > NE) E = NE;

    k_init<<<(NN + 255) / 256, 256>>>(ei, E);
    k_scatter<<<2048, 256>>>(ei, E);
    k_fin<<<(NN + 255) / 256, 256>>>(x);

    int a3N = (NN * 16 + 255) / 256;      // 16-lane-group grid

    k_agg1<<<NBLK, 256>>>(x, W1, b1, W2); // layer 1 agg + layer 2 transform
    k_agg2<<<NBLK, 256>>>(x, b2, W3);     // layer 2 agg + layer 3 transform
    k_agg3<<<a3N, 256>>>(b3, out);        // layer 3 agg -> output
}